// round 1
// baseline (speedup 1.0000x reference)
#include <cuda_runtime.h>
#include <math.h>

#define NV     12
#define BATCH  4096
#define DIM    128
#define ALPHA  0.4f
#define BETA   2.0f
#define LAMDA  2.0f

#define B_PER_BLK 2          // batch elements per block
#define THREADS   32         // 16 threads per batch element
#define CHUNK     32         // k-dims staged per chunk
#define NCHUNK    (DIM / CHUNK)     // 4
#define PITCH     36         // floats per smem row (32 data + 4 pad) => 144B stride
#define ROWS      24         // 12 A rows + 12 N rows
#define BAREA     (ROWS * PITCH)    // 864 floats per batch element

// Per-batch scratch (static device globals: no allocation in kernel_launch)
__device__ float g_loss[BATCH];
__device__ float g_sqmc[BATCH];
__device__ float g_sqac[BATCH];

__device__ __forceinline__ float dot4(float4 a, float4 b) {
    return a.x * b.x + a.y * b.y + a.z * b.z + a.w * b.w;
}
__device__ __forceinline__ float sqdiff4(float4 a, float4 b) {
    float x = a.x - b.x, y = a.y - b.y, z = a.z - b.z, w = a.w - b.w;
    return x * x + y * y + z * z + w * w;
}

__global__ __launch_bounds__(THREADS)
void pil_phase1(const float* __restrict__ SV_A, const float* __restrict__ SV_N,
                const float* __restrict__ MV_A, const float* __restrict__ MV_N)
{
    __shared__ float tile[B_PER_BLK * BAREA];   // 1728 floats = 6.9 KB
    __shared__ float nrm[B_PER_BLK * ROWS];     // 48 row norms

    const int tid = threadIdx.x;
    const int bl  = tid >> 4;        // local batch element 0/1
    const int t   = tid & 15;        // lane within batch group
    const int ti  = t >> 2;          // 0..3 -> A rows 3*ti..3*ti+2
    const int tj  = t & 3;           // 0..3 -> N rows 3*tj..3*tj+2
    const int bg0 = blockIdx.x * B_PER_BLK;

    float G[3][3] = {{0.f,0.f,0.f},{0.f,0.f,0.f},{0.f,0.f,0.f}};
    float nacc0 = 0.f, nacc1 = 0.f;   // norm partials for rows tid, tid+32

    for (int c = 0; c < NCHUNK; ++c) {
        __syncthreads();   // previous chunk fully consumed before overwrite
        // ---- stage chunk: 2b * 24 rows * 8 float4 = 384 float4, 12/thread.
        // Consecutive lanes cover consecutive k4 of one row -> perfectly
        // coalesced LDG.128 (4 lines/instr) and phase-conflict-free STS.128.
        #pragma unroll
        for (int s = 0; s < 12; ++s) {
            int f   = tid + THREADS * s;        // 0..383
            int sb  = f / (ROWS * 8);           // local batch elem
            int rem = f - sb * (ROWS * 8);
            int row = rem >> 3;                 // 0..23
            int k4  = rem & 7;
            const float* src = (row < NV)
                ? SV_A + ((size_t)row        * BATCH + (bg0 + sb)) * DIM
                : SV_N + ((size_t)(row - NV) * BATCH + (bg0 + sb)) * DIM;
            float4 v = *reinterpret_cast<const float4*>(src + c * CHUNK + k4 * 4);
            *reinterpret_cast<float4*>(&tile[sb * BAREA + row * PITCH + k4 * 4]) = v;
        }
        __syncthreads();

        // ---- norm partials: 48 rows; thread owns row tid (+ row tid+32 if tid<16)
        {
            int R = tid;                                   // 0..31
            const float* rb = &tile[(R / ROWS) * BAREA + (R % ROWS) * PITCH];
            float s0 = 0.f;
            #pragma unroll
            for (int k4 = 0; k4 < 8; ++k4) {
                float4 v = *reinterpret_cast<const float4*>(rb + k4 * 4);
                s0 += dot4(v, v);
            }
            nacc0 += s0;
            if (tid < 16) {
                int R1 = tid + 32;                         // 32..47
                const float* rb1 = &tile[(R1 / ROWS) * BAREA + (R1 % ROWS) * PITCH];
                float s1 = 0.f;
                #pragma unroll
                for (int k4 = 0; k4 < 8; ++k4) {
                    float4 v = *reinterpret_cast<const float4*>(rb1 + k4 * 4);
                    s1 += dot4(v, v);
                }
                nacc1 += s1;
            }
        }

        // ---- 3x3 register-tiled dot products (6 LDS.128 -> 36 FFMA per k4)
        const float* A0 = &tile[bl * BAREA + (3 * ti)      * PITCH];
        const float* N0 = &tile[bl * BAREA + (NV + 3 * tj) * PITCH];
        #pragma unroll
        for (int k4 = 0; k4 < 8; ++k4) {
            float4 a0 = *reinterpret_cast<const float4*>(A0 + 0 * PITCH + k4 * 4);
            float4 a1 = *reinterpret_cast<const float4*>(A0 + 1 * PITCH + k4 * 4);
            float4 a2 = *reinterpret_cast<const float4*>(A0 + 2 * PITCH + k4 * 4);
            float4 n0 = *reinterpret_cast<const float4*>(N0 + 0 * PITCH + k4 * 4);
            float4 n1 = *reinterpret_cast<const float4*>(N0 + 1 * PITCH + k4 * 4);
            float4 n2 = *reinterpret_cast<const float4*>(N0 + 2 * PITCH + k4 * 4);
            G[0][0] += dot4(a0, n0); G[0][1] += dot4(a0, n1); G[0][2] += dot4(a0, n2);
            G[1][0] += dot4(a1, n0); G[1][1] += dot4(a1, n1); G[1][2] += dot4(a1, n2);
            G[2][0] += dot4(a2, n0); G[2][1] += dot4(a2, n1); G[2][2] += dot4(a2, n2);
        }
    }

    // publish norms (row index == nrm index: [b*24 + rr])
    nrm[tid] = nacc0;
    if (tid < 16) nrm[tid + 32] = nacc1;
    __syncthreads();

    // ---- d = na + nn - 2G, local argmin with flat-index (i*12+j) first-min tie-break
    float dmin = 3.4e38f;
    int   imin = 0;
    #pragma unroll
    for (int r = 0; r < 3; ++r) {
        float na = nrm[bl * ROWS + 3 * ti + r];
        #pragma unroll
        for (int cc = 0; cc < 3; ++cc) {
            float nn = nrm[bl * ROWS + NV + 3 * tj + cc];
            float d  = na + nn - 2.f * G[r][cc];
            int   fl = (3 * ti + r) * NV + (3 * tj + cc);
            if (d < dmin || (d == dmin && fl < imin)) { dmin = d; imin = fl; }
        }
    }
    // butterfly reduce over the 16 lanes of this batch element
    #pragma unroll
    for (int o = 1; o < 16; o <<= 1) {
        float od = __shfl_xor_sync(0xffffffffu, dmin, o);
        int   oi = __shfl_xor_sync(0xffffffffu, imin, o);
        if (od < dmin || (od == dmin && oi < imin)) { dmin = od; imin = oi; }
    }

    // ---- epilogue: mv_inter, a_clstr, c_intra over 128 dims (8 dims/lane)
    const int confA = imin / NV;
    const int confN = imin - confA * NV;
    const int bg    = bg0 + bl;

    const float4* mva = reinterpret_cast<const float4*>(MV_A + (size_t)bg * DIM);
    const float4* mvn = reinterpret_cast<const float4*>(MV_N + (size_t)bg * DIM);
    const float4* fca = reinterpret_cast<const float4*>(SV_A + ((size_t)confA * BATCH + bg) * DIM);
    const float4* fcn = reinterpret_cast<const float4*>(SV_N + ((size_t)confN * BATCH + bg) * DIM);

    float smv = 0.f, sa = 0.f, sc = 0.f;
    #pragma unroll
    for (int q = 0; q < 2; ++q) {
        int k4 = t * 2 + q;            // 0..31
        float4 ma = mva[k4], mn_ = mvn[k4];
        float4 fa = fca[k4], fn  = fcn[k4];
        smv += sqdiff4(ma, mn_);
        sa  += sqdiff4(ma, fa);
        sc  += sqdiff4(mn_, fn);
    }
    #pragma unroll
    for (int o = 1; o < 16; o <<= 1) {
        smv += __shfl_xor_sync(0xffffffffu, smv, o);
        sa  += __shfl_xor_sync(0xffffffffu, sa,  o);
        sc  += __shfl_xor_sync(0xffffffffu, sc,  o);
    }

    if (t == 0) {
        float mc       = fmaxf(dmin, 0.f);          // squared distance (min)
        float mv_inter = sqrtf(smv);
        float a_cl     = sqrtf(sa);
        float c_in     = sqrtf(sc);
        float loss = LAMDA * (fmaxf(BETA - mc, 0.f) + fmaxf(BETA - mv_inter, 0.f))
                   + fmaxf(a_cl - ALPHA, 0.f) + fmaxf(c_in - ALPHA, 0.f);
        g_loss[bg] = loss;
        g_sqmc[bg] = sqrtf(mc);
        g_sqac[bg] = sqrtf(a_cl) + sqrtf(c_in);
    }
}

// Deterministic single-block final reduction (no float atomics)
__global__ __launch_bounds__(256)
void pil_phase2(float* __restrict__ out, int out_size)
{
    __shared__ float sl[256], sm[256], sa2[256], smn[256];
    __shared__ int   scnt[256];
    const int t = threadIdx.x;

    float accl = 0.f, accm = 0.f, acca = 0.f, mn = 3.4e38f;
    int cnt = 0;
    for (int i = t; i < BATCH; i += 256) {
        float l = g_loss[i];
        float q = g_sqmc[i];
        accl += l;
        cnt  += (l != 0.f) ? 1 : 0;
        accm += q;
        acca += g_sqac[i];
        mn = fminf(mn, q);
    }
    sl[t] = accl; sm[t] = accm; sa2[t] = acca; smn[t] = mn; scnt[t] = cnt;
    __syncthreads();
    for (int o = 128; o > 0; o >>= 1) {
        if (t < o) {
            sl[t]  += sl[t + o];
            sm[t]  += sm[t + o];
            sa2[t] += sa2[t + o];
            smn[t]  = fminf(smn[t], smn[t + o]);
            scnt[t] += scnt[t + o];
        }
        __syncthreads();
    }
    if (t == 0) {
        if (out_size > 0) out[0] = sl[0] / (float)BATCH;          // avg_loss
        if (out_size > 1) out[1] = (float)scnt[0];                // count_nonzero
        if (out_size > 2) out[2] = sm[0] / (float)BATCH;          // mean(sqrt(mc_inter))
        if (out_size > 3) out[3] = 0.5f * (sa2[0] / (float)BATCH);// 0.5*(mean+mean)
        if (out_size > 4) out[4] = smn[0];                        // min(sqrt(mc_inter))
        for (int i = 5; i < out_size; ++i) out[i] = 0.f;
    }
}

extern "C" void kernel_launch(void* const* d_in, const int* in_sizes, int n_in,
                              void* d_out, int out_size)
{
    const float* SV_A = (const float*)d_in[0];
    const float* SV_N = (const float*)d_in[1];
    const float* MV_A = (const float*)d_in[2];
    const float* MV_N = (const float*)d_in[3];
    (void)in_sizes; (void)n_in;

    pil_phase1<<<BATCH / B_PER_BLK, THREADS>>>(SV_A, SV_N, MV_A, MV_N);
    pil_phase2<<<1, 256>>>((float*)d_out, out_size);
}

// round 2
// speedup vs baseline: 1.1014x; 1.1014x over previous
#include <cuda_runtime.h>
#include <math.h>

#define NV     12
#define BATCH  4096
#define DIM    128
#define ALPHA  0.4f
#define BETA   2.0f
#define LAMDA  2.0f

#define B_PER_BLK 8           // batch elements per block
#define THREADS   128         // 16 threads per batch element
#define NBLOCKS   (BATCH / B_PER_BLK)   // 512
#define CHUNK     32          // k-dims staged per chunk
#define NCHUNK    (DIM / CHUNK)         // 4
#define PITCH     36          // floats per smem row (32 data + 4 pad) => 144B stride
#define ROWS      24          // 12 A rows + 12 N rows
#define BAREA     (ROWS * PITCH)        // 864 floats per batch element

// Per-block partials (static device globals: no allocation in kernel_launch)
__device__ float g_pl[NBLOCKS];    // sum of losses
__device__ float g_pc[NBLOCKS];    // count of nonzero losses
__device__ float g_pm[NBLOCKS];    // sum of sqrt(mc_inter)
__device__ float g_pa[NBLOCKS];    // sum of sqrt(a_clstr)+sqrt(c_intra)
__device__ float g_pmin[NBLOCKS];  // min of sqrt(mc_inter)

__device__ __forceinline__ float dot4(float4 a, float4 b) {
    return a.x * b.x + a.y * b.y + a.z * b.z + a.w * b.w;
}
__device__ __forceinline__ float sqdiff4(float4 a, float4 b) {
    float x = a.x - b.x, y = a.y - b.y, z = a.z - b.z, w = a.w - b.w;
    return x * x + y * y + z * z + w * w;
}

__global__ __launch_bounds__(THREADS)
void pil_phase1(const float* __restrict__ SV_A, const float* __restrict__ SV_N,
                const float* __restrict__ MV_A, const float* __restrict__ MV_N)
{
    __shared__ float tile[B_PER_BLK * BAREA];   // 6912 floats = 27.6 KB
    __shared__ float nrm[B_PER_BLK * ROWS];     // 192 row norms
    __shared__ float r_loss[B_PER_BLK], r_cnt[B_PER_BLK];
    __shared__ float r_mc[B_PER_BLK], r_ac[B_PER_BLK], r_mn[B_PER_BLK];

    const int tid = threadIdx.x;
    const int bl  = tid >> 4;        // local batch element 0..7
    const int t   = tid & 15;        // lane within batch group
    const int ti  = t >> 2;          // 0..3 -> A rows 3*ti..3*ti+2
    const int tj  = t & 3;           // 0..3 -> N rows 3*tj..3*tj+2
    const int bg0 = blockIdx.x * B_PER_BLK;

    float G[3][3] = {{0.f,0.f,0.f},{0.f,0.f,0.f},{0.f,0.f,0.f}};
    float nacc0 = 0.f, nacc1 = 0.f;   // norm partials for rows tid, tid+128

    for (int c = 0; c < NCHUNK; ++c) {
        __syncthreads();   // previous chunk fully consumed before overwrite
        // ---- stage chunk: 8b * 24 rows * 8 float4 = 1536 float4, 12/thread.
        // Consecutive lanes cover consecutive k4 of one row -> coalesced
        // LDG.128 and phase-conflict-free STS.128 (PITCH=36 floats).
        #pragma unroll
        for (int s = 0; s < 12; ++s) {
            int f   = tid + THREADS * s;        // 0..1535
            int sb  = f / (ROWS * 8);           // local batch elem 0..7
            int rem = f - sb * (ROWS * 8);
            int row = rem >> 3;                 // 0..23
            int k4  = rem & 7;
            const float* src = (row < NV)
                ? SV_A + ((size_t)row        * BATCH + (bg0 + sb)) * DIM
                : SV_N + ((size_t)(row - NV) * BATCH + (bg0 + sb)) * DIM;
            float4 v = *reinterpret_cast<const float4*>(src + c * CHUNK + k4 * 4);
            *reinterpret_cast<float4*>(&tile[sb * BAREA + row * PITCH + k4 * 4]) = v;
        }
        __syncthreads();

        // ---- norm partials: 192 rows; thread owns row tid (+ tid+128 if tid<64)
        {
            int R  = tid;
            int sb = R / ROWS, row = R - sb * ROWS;
            const float* rb = &tile[sb * BAREA + row * PITCH];
            float s0 = 0.f;
            #pragma unroll
            for (int k4 = 0; k4 < 8; ++k4) {
                float4 v = *reinterpret_cast<const float4*>(rb + k4 * 4);
                s0 += dot4(v, v);
            }
            nacc0 += s0;
            if (tid < B_PER_BLK * ROWS - THREADS) {       // tid < 64
                int R1  = tid + THREADS;
                int sb1 = R1 / ROWS, row1 = R1 - sb1 * ROWS;
                const float* rb1 = &tile[sb1 * BAREA + row1 * PITCH];
                float s1 = 0.f;
                #pragma unroll
                for (int k4 = 0; k4 < 8; ++k4) {
                    float4 v = *reinterpret_cast<const float4*>(rb1 + k4 * 4);
                    s1 += dot4(v, v);
                }
                nacc1 += s1;
            }
        }

        // ---- 3x3 register-tiled dot products (6 LDS.128 -> 36 FFMA per k4)
        const float* A0 = &tile[bl * BAREA + (3 * ti)      * PITCH];
        const float* N0 = &tile[bl * BAREA + (NV + 3 * tj) * PITCH];
        #pragma unroll
        for (int k4 = 0; k4 < 8; ++k4) {
            float4 a0 = *reinterpret_cast<const float4*>(A0 + 0 * PITCH + k4 * 4);
            float4 a1 = *reinterpret_cast<const float4*>(A0 + 1 * PITCH + k4 * 4);
            float4 a2 = *reinterpret_cast<const float4*>(A0 + 2 * PITCH + k4 * 4);
            float4 n0 = *reinterpret_cast<const float4*>(N0 + 0 * PITCH + k4 * 4);
            float4 n1 = *reinterpret_cast<const float4*>(N0 + 1 * PITCH + k4 * 4);
            float4 n2 = *reinterpret_cast<const float4*>(N0 + 2 * PITCH + k4 * 4);
            G[0][0] += dot4(a0, n0); G[0][1] += dot4(a0, n1); G[0][2] += dot4(a0, n2);
            G[1][0] += dot4(a1, n0); G[1][1] += dot4(a1, n1); G[1][2] += dot4(a1, n2);
            G[2][0] += dot4(a2, n0); G[2][1] += dot4(a2, n1); G[2][2] += dot4(a2, n2);
        }
    }

    // publish norms (nrm index = sb*24 + row, same as row ownership above)
    nrm[tid] = nacc0;
    if (tid < B_PER_BLK * ROWS - THREADS) nrm[tid + THREADS] = nacc1;
    __syncthreads();

    // ---- d = na + nn - 2G, local argmin with flat-index (i*12+j) tie-break
    float dmin = 3.4e38f;
    int   imin = 0;
    #pragma unroll
    for (int r = 0; r < 3; ++r) {
        float na = nrm[bl * ROWS + 3 * ti + r];
        #pragma unroll
        for (int cc = 0; cc < 3; ++cc) {
            float nn = nrm[bl * ROWS + NV + 3 * tj + cc];
            float d  = na + nn - 2.f * G[r][cc];
            int   fl = (3 * ti + r) * NV + (3 * tj + cc);
            if (d < dmin || (d == dmin && fl < imin)) { dmin = d; imin = fl; }
        }
    }
    // butterfly reduce over the 16 lanes of this batch group (within-warp)
    #pragma unroll
    for (int o = 1; o < 16; o <<= 1) {
        float od = __shfl_xor_sync(0xffffffffu, dmin, o);
        int   oi = __shfl_xor_sync(0xffffffffu, imin, o);
        if (od < dmin || (od == dmin && oi < imin)) { dmin = od; imin = oi; }
    }

    // ---- epilogue: mv_inter, a_clstr, c_intra over 128 dims (8 dims/lane)
    const int confA = imin / NV;
    const int confN = imin - confA * NV;
    const int bg    = bg0 + bl;

    const float4* mva = reinterpret_cast<const float4*>(MV_A + (size_t)bg * DIM);
    const float4* mvn = reinterpret_cast<const float4*>(MV_N + (size_t)bg * DIM);
    const float4* fca = reinterpret_cast<const float4*>(SV_A + ((size_t)confA * BATCH + bg) * DIM);
    const float4* fcn = reinterpret_cast<const float4*>(SV_N + ((size_t)confN * BATCH + bg) * DIM);

    float smv = 0.f, sa = 0.f, sc = 0.f;
    #pragma unroll
    for (int q = 0; q < 2; ++q) {
        int k4 = t * 2 + q;            // 0..31
        float4 ma = mva[k4], mn_ = mvn[k4];
        float4 fa = fca[k4], fn  = fcn[k4];
        smv += sqdiff4(ma, mn_);
        sa  += sqdiff4(ma, fa);
        sc  += sqdiff4(mn_, fn);
    }
    #pragma unroll
    for (int o = 1; o < 16; o <<= 1) {
        smv += __shfl_xor_sync(0xffffffffu, smv, o);
        sa  += __shfl_xor_sync(0xffffffffu, sa,  o);
        sc  += __shfl_xor_sync(0xffffffffu, sc,  o);
    }

    if (t == 0) {
        float mc       = fmaxf(dmin, 0.f);          // min squared distance
        float mv_inter = sqrtf(smv);
        float a_cl     = sqrtf(sa);
        float c_in     = sqrtf(sc);
        float loss = LAMDA * (fmaxf(BETA - mc, 0.f) + fmaxf(BETA - mv_inter, 0.f))
                   + fmaxf(a_cl - ALPHA, 0.f) + fmaxf(c_in - ALPHA, 0.f);
        float sqmc = sqrtf(mc);
        r_loss[bl] = loss;
        r_cnt[bl]  = (loss != 0.f) ? 1.f : 0.f;
        r_mc[bl]   = sqmc;
        r_ac[bl]   = sqrtf(a_cl) + sqrtf(c_in);
        r_mn[bl]   = sqmc;
    }
    __syncthreads();

    // ---- per-block partial (fixed order -> deterministic)
    if (tid == 0) {
        float sl = 0.f, sn = 0.f, sm = 0.f, sa2 = 0.f, mn = 3.4e38f;
        #pragma unroll
        for (int i = 0; i < B_PER_BLK; ++i) {
            sl  += r_loss[i];
            sn  += r_cnt[i];
            sm  += r_mc[i];
            sa2 += r_ac[i];
            mn   = fminf(mn, r_mn[i]);
        }
        g_pl[blockIdx.x]   = sl;
        g_pc[blockIdx.x]   = sn;
        g_pm[blockIdx.x]   = sm;
        g_pa[blockIdx.x]   = sa2;
        g_pmin[blockIdx.x] = mn;
    }
}

// Deterministic single-block final reduction over 512 partials
__global__ __launch_bounds__(512)
void pil_phase2(float* __restrict__ out, int out_size)
{
    __shared__ float sl[512], sc[512], sm[512], sa[512], sn[512];
    const int t = threadIdx.x;

    sl[t] = g_pl[t];
    sc[t] = g_pc[t];
    sm[t] = g_pm[t];
    sa[t] = g_pa[t];
    sn[t] = g_pmin[t];
    __syncthreads();
    for (int o = 256; o > 0; o >>= 1) {
        if (t < o) {
            sl[t] += sl[t + o];
            sc[t] += sc[t + o];
            sm[t] += sm[t + o];
            sa[t] += sa[t + o];
            sn[t]  = fminf(sn[t], sn[t + o]);
        }
        __syncthreads();
    }
    if (t == 0) {
        const float inv = 1.f / (float)BATCH;
        if (out_size > 0) out[0] = sl[0] * inv;          // avg_loss
        if (out_size > 1) out[1] = sc[0];                // count_nonzero
        if (out_size > 2) out[2] = sm[0] * inv;          // mean(sqrt(mc_inter))
        if (out_size > 3) out[3] = 0.5f * sa[0] * inv;   // 0.5*(mean+mean)
        if (out_size > 4) out[4] = sn[0];                // min(sqrt(mc_inter))
        for (int i = 5; i < out_size; ++i) out[i] = 0.f;
    }
}

extern "C" void kernel_launch(void* const* d_in, const int* in_sizes, int n_in,
                              void* d_out, int out_size)
{
    const float* SV_A = (const float*)d_in[0];
    const float* SV_N = (const float*)d_in[1];
    const float* MV_A = (const float*)d_in[2];
    const float* MV_N = (const float*)d_in[3];
    (void)in_sizes; (void)n_in;

    pil_phase1<<<NBLOCKS, THREADS>>>(SV_A, SV_N, MV_A, MV_N);
    pil_phase2<<<1, 512>>>((float*)d_out, out_size);
}